// round 12
// baseline (speedup 1.0000x reference)
#include <cuda_runtime.h>
#include <cmath>

#define NLAY 2
#define BATCH 4
#define SEQ 1024
#define HIDD 512
#define NH 8
#define NE 8
#define FFN_D 1024
#define NTOK 4096      // BATCH*SEQ
#define PROJ 4096      // NH*HIDD

// ---------------- scratch (device globals; no allocation allowed) ----------------
__device__ float g_q[(size_t)NTOK * PROJ];
__device__ float g_k[(size_t)NTOK * PROJ];
__device__ float g_v[(size_t)NTOK * PROJ];
__device__ float g_s[(size_t)32 * SEQ * SEQ];
__device__ float g_cat[(size_t)NTOK * PROJ];
__device__ float g_att[(size_t)NTOK * HIDD];
__device__ float g_x[(size_t)NTOK * HIDD];
__device__ float g_h[(size_t)NTOK * FFN_D];
__device__ float g_moe[(size_t)NTOK * HIDD];
__device__ int   g_sel[NTOK];
__device__ float g_wsel[NTOK];
__device__ int   g_perm[NTOK];
__device__ int   g_cnt[NE];
__device__ int   g_off[NE + 1];

// ---------------- 128x128x8 SGEMM, 8x8 per thread ----------------
// MODE 0: normal (batched via z strides). MODE 1: MoE GEMM1 (gather A rows via perm, +bias, relu).
// MODE 2: MoE GEMM2 (A contiguous permuted, +bias, scale by wsel, scatter C rows via perm).
template <int TRANSB, int MODE>
__global__ void __launch_bounds__(256, 2)
gemm128(const float* __restrict__ A, const float* __restrict__ B,
        const float* __restrict__ bias, float* __restrict__ C,
        int M, int N, int K, int lda, int ldb, int ldc,
        long sA, long sB, long sCb, long sCh, int sBias,
        const int* __restrict__ cnt, const int* __restrict__ off,
        const int* __restrict__ perm, const float* __restrict__ wsel)
{
    __shared__ float As[8 * 132];
    __shared__ float Bs[8 * 132];

    const int z = blockIdx.z;
    const int mBase = blockIdx.y * 128;
    const int nBase = blockIdx.x * 128;

    int Meff = M;
    int rowOff = 0;
    if (MODE != 0) {
        Meff = cnt[z];
        if (mBase >= Meff) return;
        rowOff = off[z];
    }
    const float* Ab = A + (MODE == 0 ? (long)z * sA : 0L);
    const float* Bb = B + (long)z * sB;
    float* Cb = (MODE == 0) ? (C + (long)(z >> 3) * sCb + (long)(z & 7) * sCh) : C;

    const int tid  = threadIdx.x;
    const int arow = tid >> 1;
    const int ak4  = (tid & 1) * 4;
    const int ty   = tid >> 4;
    const int tx   = tid & 15;

    long aOff;
    {
        int r = mBase + arow;
        if (MODE == 1) {
            int rc = (r < Meff) ? r : (Meff - 1);
            aOff = (long)perm[rowOff + rc] * lda;
        } else if (MODE == 2) {
            int rc = (r < Meff) ? r : (Meff - 1);
            aOff = (long)(rowOff + rc) * lda;
        } else {
            aOff = (long)r * lda;
        }
    }

    long bOff;
    int bk, bn;
    if (TRANSB == 0) { bk = tid >> 5; bn = (tid & 31) * 4; bOff = (long)bk * ldb + nBase + bn; }
    else             { bn = tid >> 1; bk = (tid & 1) * 4;  bOff = (long)(nBase + bn) * ldb + bk; }

    float acc[8][8];
#pragma unroll
    for (int i = 0; i < 8; i++)
#pragma unroll
        for (int j = 0; j < 8; j++) acc[i][j] = 0.f;

    for (int kt = 0; kt < K; kt += 8) {
        float4 av = *(const float4*)(Ab + aOff + kt + ak4);
        As[(ak4 + 0) * 132 + arow] = av.x;
        As[(ak4 + 1) * 132 + arow] = av.y;
        As[(ak4 + 2) * 132 + arow] = av.z;
        As[(ak4 + 3) * 132 + arow] = av.w;
        if (TRANSB == 0) {
            float4 bv = *(const float4*)(Bb + (long)kt * ldb + bOff);
            *(float4*)&Bs[bk * 132 + bn] = bv;
        } else {
            float4 bv = *(const float4*)(Bb + bOff + kt);
            Bs[(bk + 0) * 132 + bn] = bv.x;
            Bs[(bk + 1) * 132 + bn] = bv.y;
            Bs[(bk + 2) * 132 + bn] = bv.z;
            Bs[(bk + 3) * 132 + bn] = bv.w;
        }
        __syncthreads();
#pragma unroll
        for (int k = 0; k < 8; k++) {
            float a[8], b[8];
            *(float4*)(a)     = *(const float4*)&As[k * 132 + ty * 8];
            *(float4*)(a + 4) = *(const float4*)&As[k * 132 + ty * 8 + 4];
            *(float4*)(b)     = *(const float4*)&Bs[k * 132 + tx * 8];
            *(float4*)(b + 4) = *(const float4*)&Bs[k * 132 + tx * 8 + 4];
#pragma unroll
            for (int i = 0; i < 8; i++)
#pragma unroll
                for (int j = 0; j < 8; j++)
                    acc[i][j] = fmaf(a[i], b[j], acc[i][j]);
        }
        __syncthreads();
    }

    const float* bb = bias ? (bias + (long)z * sBias) : nullptr;
    float bcol[8];
#pragma unroll
    for (int j = 0; j < 8; j++) bcol[j] = bb ? bb[nBase + tx * 8 + j] : 0.f;

#pragma unroll
    for (int i = 0; i < 8; i++) {
        int r = mBase + ty * 8 + i;
        if (MODE != 0 && r >= Meff) continue;
        long crow;
        float scale = 1.f;
        if (MODE == 0)      crow = (long)r * ldc;
        else if (MODE == 1) crow = (long)(rowOff + r) * ldc;
        else { int tok = perm[rowOff + r]; crow = (long)tok * ldc; scale = wsel[tok]; }
#pragma unroll
        for (int j = 0; j < 8; j++) {
            float vv = acc[i][j] + bcol[j];
            if (MODE == 1) vv = fmaxf(vv, 0.f);
            if (MODE == 2) vv *= scale;
            Cb[crow + nBase + tx * 8 + j] = vv;
        }
    }
}

// ---------------- row softmax over [32*SEQ, SEQ], optional causal mask ----------------
__global__ void softmax_kernel(float* __restrict__ S, int masked)
{
    const int r = blockIdx.x;
    const int q = r & (SEQ - 1);
    float* row = S + (long)r * SEQ;
    const int t = threadIdx.x;  // 256

    __shared__ float red[32];
    float v[4];
    float mx = -INFINITY;
#pragma unroll
    for (int i = 0; i < 4; i++) {
        int c = t + i * 256;
        float x = row[c];
        if (masked && c > q) x = -INFINITY;
        v[i] = x;
        mx = fmaxf(mx, x);
    }
    for (int o = 16; o; o >>= 1) mx = fmaxf(mx, __shfl_xor_sync(0xffffffffu, mx, o));
    if ((t & 31) == 0) red[t >> 5] = mx;
    __syncthreads();
    if (t < 32) {
        float m2 = (t < 8) ? red[t] : -INFINITY;
        for (int o = 4; o; o >>= 1) m2 = fmaxf(m2, __shfl_xor_sync(0xffffffffu, m2, o));
        if (t == 0) red[0] = m2;
    }
    __syncthreads();
    mx = red[0];
    __syncthreads();

    float s = 0.f;
#pragma unroll
    for (int i = 0; i < 4; i++) {
        v[i] = __expf(v[i] - mx);   // exp(-inf)=0
        s += v[i];
    }
    for (int o = 16; o; o >>= 1) s += __shfl_xor_sync(0xffffffffu, s, o);
    if ((t & 31) == 0) red[t >> 5] = s;
    __syncthreads();
    if (t < 32) {
        float s2 = (t < 8) ? red[t] : 0.f;
        for (int o = 4; o; o >>= 1) s2 += __shfl_xor_sync(0xffffffffu, s2, o);
        if (t == 0) red[0] = s2;
    }
    __syncthreads();
    float inv = 1.f / red[0];
#pragma unroll
    for (int i = 0; i < 4; i++) row[t + i * 256] = v[i] * inv;
}

// ---------------- out = LayerNorm(a + xin), row = 512 ----------------
__global__ void add_ln_kernel(const float* __restrict__ a, const float* __restrict__ xin,
                              const float* __restrict__ g, const float* __restrict__ b,
                              float* __restrict__ out)
{
    const int row = blockIdx.x;
    const int t = threadIdx.x;  // 128
    const long base = (long)row * HIDD;
    __shared__ float red[4];

    float v[4];
    float s = 0.f;
#pragma unroll
    for (int i = 0; i < 4; i++) {
        int c = t + i * 128;
        v[i] = a[base + c] + xin[base + c];
        s += v[i];
    }
    for (int o = 16; o; o >>= 1) s += __shfl_xor_sync(0xffffffffu, s, o);
    if ((t & 31) == 0) red[t >> 5] = s;
    __syncthreads();
    float mean = (red[0] + red[1] + red[2] + red[3]) * (1.f / 512.f);

    float var = 0.f;
#pragma unroll
    for (int i = 0; i < 4; i++) { float d = v[i] - mean; var += d * d; }
    for (int o = 16; o; o >>= 1) var += __shfl_xor_sync(0xffffffffu, var, o);
    __syncthreads();
    if ((t & 31) == 0) red[t >> 5] = var;
    __syncthreads();
    float rs = rsqrtf((red[0] + red[1] + red[2] + red[3]) * (1.f / 512.f) + 1e-5f);

#pragma unroll
    for (int i = 0; i < 4; i++) {
        int c = t + i * 128;
        out[base + c] = g[c] * (v[i] - mean) * rs + b[c];
    }
}

// ---------------- gating: logits -> 2nd-largest expert + weight ----------------
__global__ void gate_kernel(const float* __restrict__ x, const float* __restrict__ gw,
                            const float* __restrict__ gb, int* __restrict__ sel,
                            float* __restrict__ wsel)
{
    const int warp = threadIdx.x >> 5;
    const int lane = threadIdx.x & 31;
    const int t = blockIdx.x * 8 + warp;
    const float* xr = x + (long)t * HIDD;
    float p[8] = {0, 0, 0, 0, 0, 0, 0, 0};
    for (int k = lane; k < HIDD; k += 32) {
        float xv = xr[k];
        const float4* gwp = (const float4*)(gw + k * 8);
        float4 g0 = gwp[0], g1 = gwp[1];
        p[0] = fmaf(xv, g0.x, p[0]); p[1] = fmaf(xv, g0.y, p[1]);
        p[2] = fmaf(xv, g0.z, p[2]); p[3] = fmaf(xv, g0.w, p[3]);
        p[4] = fmaf(xv, g1.x, p[4]); p[5] = fmaf(xv, g1.y, p[5]);
        p[6] = fmaf(xv, g1.z, p[6]); p[7] = fmaf(xv, g1.w, p[7]);
    }
#pragma unroll
    for (int e = 0; e < 8; e++)
        for (int o = 16; o; o >>= 1) p[e] += __shfl_xor_sync(0xffffffffu, p[e], o);
    if (lane == 0) {
#pragma unroll
        for (int e = 0; e < 8; e++) p[e] += gb[e];
        int i1 = 0;
#pragma unroll
        for (int e = 1; e < 8; e++) if (p[e] > p[i1]) i1 = e;
        int i2 = (i1 == 0) ? 1 : 0;
#pragma unroll
        for (int e = 0; e < 8; e++) if (e != i1 && p[e] > p[i2]) i2 = e;
        sel[t]  = i2;
        wsel[t] = 1.f / (1.f + __expf(p[i1] - p[i2]));  // g2/(g1+g2)
    }
}

// ---------------- stable counting-sort of tokens by expert (single block) ----------------
__global__ void perm_kernel(const int* __restrict__ sel, int* __restrict__ perm,
                            int* __restrict__ cnt, int* __restrict__ off)
{
    __shared__ int lc[256][8];
    __shared__ int soff[9];
    const int t = threadIdx.x;
    const int t0 = t * 16;
    int c[8] = {0, 0, 0, 0, 0, 0, 0, 0};
    for (int i = 0; i < 16; i++) c[sel[t0 + i]]++;
#pragma unroll
    for (int e = 0; e < 8; e++) lc[t][e] = c[e];
    __syncthreads();
    if (t == 0) {
        int run[8] = {0, 0, 0, 0, 0, 0, 0, 0};
        for (int i = 0; i < 256; i++)
            for (int e = 0; e < 8; e++) { int tmp = lc[i][e]; lc[i][e] = run[e]; run[e] += tmp; }
        int o = 0;
        for (int e = 0; e < 8; e++) { soff[e] = o; off[e] = o; cnt[e] = run[e]; o += run[e]; }
        soff[8] = o; off[8] = o;
    }
    __syncthreads();
    int pos[8];
#pragma unroll
    for (int e = 0; e < 8; e++) pos[e] = soff[e] + lc[t][e];
    for (int i = 0; i < 16; i++) { int e = sel[t0 + i]; perm[pos[e]++] = t0 + i; }
}

// ---------------- host orchestration ----------------
extern "C" void kernel_launch(void* const* d_in, const int* in_sizes, int n_in,
                              void* d_out, int out_size)
{
    const float* x_in = (const float*)d_in[0];
    const float* enc  = (const float*)d_in[1];
    const float* wq = (const float*)d_in[2];
    const float* bq = (const float*)d_in[3];
    const float* wk = (const float*)d_in[4];
    const float* bk = (const float*)d_in[5];
    const float* wv = (const float*)d_in[6];
    const float* bv = (const float*)d_in[7];
    const float* wo = (const float*)d_in[8];
    const float* bo = (const float*)d_in[9];
    const float* gw = (const float*)d_in[10];
    const float* gb = (const float*)d_in[11];
    const float* w1 = (const float*)d_in[12];
    const float* b1 = (const float*)d_in[13];
    const float* w2 = (const float*)d_in[14];
    const float* b2 = (const float*)d_in[15];
    const float* lg = (const float*)d_in[16];
    const float* lb = (const float*)d_in[17];

    float *q, *k, *v, *s, *cat, *att, *x, *h, *moe, *wsel;
    int *sel, *perm, *cnt, *off;
    cudaGetSymbolAddress((void**)&q,    g_q);
    cudaGetSymbolAddress((void**)&k,    g_k);
    cudaGetSymbolAddress((void**)&v,    g_v);
    cudaGetSymbolAddress((void**)&s,    g_s);
    cudaGetSymbolAddress((void**)&cat,  g_cat);
    cudaGetSymbolAddress((void**)&att,  g_att);
    cudaGetSymbolAddress((void**)&x,    g_x);
    cudaGetSymbolAddress((void**)&h,    g_h);
    cudaGetSymbolAddress((void**)&moe,  g_moe);
    cudaGetSymbolAddress((void**)&sel,  g_sel);
    cudaGetSymbolAddress((void**)&wsel, g_wsel);
    cudaGetSymbolAddress((void**)&perm, g_perm);
    cudaGetSymbolAddress((void**)&cnt,  g_cnt);
    cudaGetSymbolAddress((void**)&off,  g_off);

    cudaMemcpyAsync(x, x_in, (size_t)NTOK * HIDD * sizeof(float), cudaMemcpyDeviceToDevice);

    for (int l = 0; l < NLAY; l++) {
        for (int pass = 0; pass < 2; pass++) {   // 0 = masked self-attn, 1 = cross-attn
            const int wi = l * 2 + pass;
            const float* WQ = wq + (size_t)wi * HIDD * PROJ;
            const float* WK = wk + (size_t)wi * HIDD * PROJ;
            const float* WV = wv + (size_t)wi * HIDD * PROJ;
            const float* WO = wo + (size_t)wi * PROJ * HIDD;
            const float* BQ = bq + (size_t)wi * PROJ;
            const float* BK = bk + (size_t)wi * PROJ;
            const float* BV = bv + (size_t)wi * PROJ;
            const float* BO = bo + (size_t)wi * HIDD;
            const float* qin = (pass == 0) ? x : enc;
            const float* kin = (pass == 0) ? x : enc;
            const float* vin = x;   // self: x ; cross: values from current x (faithful)

            // projections [4096,512] @ [512,4096]
            gemm128<0, 0><<<dim3(32, 32, 1), 256>>>(qin, WQ, BQ, q, NTOK, PROJ, HIDD,
                HIDD, PROJ, PROJ, 0, 0, 0, 0, 0, nullptr, nullptr, nullptr, nullptr);
            gemm128<0, 0><<<dim3(32, 32, 1), 256>>>(kin, WK, BK, k, NTOK, PROJ, HIDD,
                HIDD, PROJ, PROJ, 0, 0, 0, 0, 0, nullptr, nullptr, nullptr, nullptr);
            gemm128<0, 0><<<dim3(32, 32, 1), 256>>>(vin, WV, BV, v, NTOK, PROJ, HIDD,
                HIDD, PROJ, PROJ, 0, 0, 0, 0, 0, nullptr, nullptr, nullptr, nullptr);

            // scores[bh] = Q[bh] @ K[bh]^T  (32 x [1024,1024,512], NT)
            gemm128<1, 0><<<dim3(8, 8, 32), 256>>>(q, k, nullptr, s, SEQ, SEQ, HIDD,
                HIDD, HIDD, SEQ, 524288L, 524288L, 8388608L, 1048576L, 0,
                nullptr, nullptr, nullptr, nullptr);

            softmax_kernel<<<32 * SEQ, 256>>>(s, pass == 0 ? 1 : 0);

            // out[bh] = P @ V -> concat [b, s, h*512 + d]
            gemm128<0, 0><<<dim3(4, 8, 32), 256>>>(s, v, nullptr, cat, SEQ, HIDD, SEQ,
                SEQ, HIDD, PROJ, 1048576L, 524288L, 4194304L, 512L, 0,
                nullptr, nullptr, nullptr, nullptr);

            // attn out = concat @ Wo + bo
            gemm128<0, 0><<<dim3(4, 32, 1), 256>>>(cat, WO, BO, att, NTOK, HIDD, PROJ,
                PROJ, HIDD, HIDD, 0, 0, 0, 0, 0, nullptr, nullptr, nullptr, nullptr);

            add_ln_kernel<<<NTOK, 128>>>(att, x, lg + (size_t)(l * 3 + pass) * HIDD,
                                         lb + (size_t)(l * 3 + pass) * HIDD, x);
        }

        // ---- MoE (only the 2nd-largest expert survives, per reference quirk) ----
        gate_kernel<<<NTOK / 8, 256>>>(x, gw + (size_t)l * HIDD * NE, gb + (size_t)l * NE,
                                       sel, wsel);
        perm_kernel<<<1, 256>>>(sel, perm, cnt, off);

        gemm128<0, 1><<<dim3(FFN_D / 128, NTOK / 128, NE), 256>>>(
            x, w1 + (size_t)l * NE * HIDD * FFN_D, b1 + (size_t)l * NE * FFN_D, h,
            0, FFN_D, HIDD, HIDD, FFN_D, FFN_D,
            0, (long)HIDD * FFN_D, 0, 0, FFN_D, cnt, off, perm, nullptr);

        gemm128<0, 2><<<dim3(HIDD / 128, NTOK / 128, NE), 256>>>(
            h, w2 + (size_t)l * NE * FFN_D * HIDD, b2 + (size_t)l * NE * HIDD, moe,
            0, HIDD, FFN_D, FFN_D, HIDD, HIDD,
            0, (long)FFN_D * HIDD, 0, 0, HIDD, cnt, off, perm, wsel);

        add_ln_kernel<<<NTOK, 128>>>(moe, x, lg + (size_t)(l * 3 + 2) * HIDD,
                                     lb + (size_t)(l * 3 + 2) * HIDD, x);
    }

    cudaMemcpyAsync(d_out, x, (size_t)out_size * sizeof(float), cudaMemcpyDeviceToDevice);
}

// round 13
// speedup vs baseline: 1.2718x; 1.2718x over previous
#include <cuda_runtime.h>
#include <cmath>

#define NLAY 2
#define BATCH 4
#define SEQ 1024
#define HIDD 512
#define NH 8
#define NE 8
#define FFN_D 1024
#define NTOK 4096      // BATCH*SEQ
#define PROJ 4096      // NH*HIDD

// ---------------- scratch (device globals; no allocation allowed) ----------------
__device__ float g_q[(size_t)NTOK * PROJ];
__device__ float g_k[(size_t)NTOK * PROJ];
__device__ float g_v[(size_t)NTOK * PROJ];
__device__ float g_s[(size_t)32 * SEQ * SEQ];
__device__ float g_cat[(size_t)NTOK * PROJ];
__device__ float g_att[(size_t)NTOK * HIDD];
__device__ float g_x[(size_t)NTOK * HIDD];
__device__ float g_h[(size_t)NTOK * FFN_D];
__device__ float g_moe[(size_t)NTOK * HIDD];
__device__ int   g_sel[NTOK];
__device__ float g_wsel[NTOK];
__device__ int   g_perm[NTOK];
__device__ int   g_cnt[NE];
__device__ int   g_off[NE + 1];

// ---------------- tf32 helpers ----------------
__device__ __forceinline__ void split2(float v, float& hi, float& lo) {
    hi = __uint_as_float(__float_as_uint(v) & 0xFFFFE000u);  // keep tf32's 10 mantissa bits
    lo = v - hi;
}

__device__ __forceinline__ void mma_tf32(float* c, const unsigned* a, const unsigned* b) {
    asm volatile(
        "mma.sync.aligned.m16n8k8.row.col.f32.tf32.tf32.f32 "
        "{%0,%1,%2,%3}, {%4,%5,%6,%7}, {%8,%9}, {%0,%1,%2,%3};\n"
        : "+f"(c[0]), "+f"(c[1]), "+f"(c[2]), "+f"(c[3])
        : "r"(a[0]), "r"(a[1]), "r"(a[2]), "r"(a[3]), "r"(b[0]), "r"(b[1]));
}

// ---------------- 128x128 GEMM, tensor cores (tf32 3-term split), KT=16 ----------------
// MODE 0: normal (batched via z strides). MODE 1: MoE GEMM1 (gather A rows via perm, +bias, relu).
// MODE 2: MoE GEMM2 (A contiguous permuted, +bias, scale by wsel, scatter C rows via perm).
template <int TRANSB, int MODE>
__global__ void __launch_bounds__(256, 2)
gemm_t32(const float* __restrict__ A, const float* __restrict__ B,
         const float* __restrict__ bias, float* __restrict__ C,
         int M, int N, int K, int lda, int ldb, int ldc,
         long sA, long sB, long sCb, long sCh, int sBias,
         const int* __restrict__ cnt, const int* __restrict__ off,
         const int* __restrict__ perm, const float* __restrict__ wsel)
{
    __shared__ float Ah[128 * 20];   // [m][k], stride 20 (conflict-free frag loads)
    __shared__ float Al[128 * 20];
    __shared__ float Bh[16 * 132];   // [k][n], stride 132
    __shared__ float Bl[16 * 132];

    const int z = blockIdx.z;
    const int mBase = blockIdx.y * 128;
    const int nBase = blockIdx.x * 128;

    int Meff = M;
    int rowOff = 0;
    if (MODE != 0) {
        Meff = cnt[z];
        if (mBase >= Meff) return;
        rowOff = off[z];
    }
    const float* Ab = A + (MODE == 0 ? (long)z * sA : 0L);
    const float* Bb = B + (long)z * sB;
    float* Cb = (MODE == 0) ? (C + (long)(z >> 3) * sCb + (long)(z & 7) * sCh) : C;

    const int tid  = threadIdx.x;
    const int lane = tid & 31;
    const int wid  = tid >> 5;
    const int wm   = (wid & 1) * 64;   // warp M offset (2 warps over M)
    const int wn   = (wid >> 1) * 32;  // warp N offset (4 warps over N)

    // A-load rows: each thread loads rows (tid>>2) and (tid>>2)+64, 4 k-floats each
    long aRow0, aRow1;
    {
        int r0 = mBase + (tid >> 2);
        int r1 = r0 + 64;
        if (MODE == 1) {
            int c0 = (r0 < Meff) ? r0 : (Meff - 1);
            int c1 = (r1 < Meff) ? r1 : (Meff - 1);
            aRow0 = (long)perm[rowOff + c0] * lda;
            aRow1 = (long)perm[rowOff + c1] * lda;
        } else if (MODE == 2) {
            int c0 = (r0 < Meff) ? r0 : (Meff - 1);
            int c1 = (r1 < Meff) ? r1 : (Meff - 1);
            aRow0 = (long)(rowOff + c0) * lda;
            aRow1 = (long)(rowOff + c1) * lda;
        } else {
            aRow0 = (long)r0 * lda;
            aRow1 = (long)r1 * lda;
        }
    }
    const int am0 = tid >> 2;            // smem m row for slot0 (slot1: +64)
    const int ak4 = (tid & 3) * 4;       // k offset of this thread's float4

    float acc[4][4][4];
#pragma unroll
    for (int mt = 0; mt < 4; mt++)
#pragma unroll
        for (int nt = 0; nt < 4; nt++)
#pragma unroll
            for (int c = 0; c < 4; c++) acc[mt][nt][c] = 0.f;

    for (int kt = 0; kt < K; kt += 16) {
        __syncthreads();
        // ---- A tile: 128 rows x 16 k ----
        {
            float4 av0 = *(const float4*)(Ab + aRow0 + kt + ak4);
            float4 av1 = *(const float4*)(Ab + aRow1 + kt + ak4);
            float h, l;
            int b0 = am0 * 20 + ak4;
            split2(av0.x, h, l); Ah[b0 + 0] = h; Al[b0 + 0] = l;
            split2(av0.y, h, l); Ah[b0 + 1] = h; Al[b0 + 1] = l;
            split2(av0.z, h, l); Ah[b0 + 2] = h; Al[b0 + 2] = l;
            split2(av0.w, h, l); Ah[b0 + 3] = h; Al[b0 + 3] = l;
            int b1 = b0 + 64 * 20;
            split2(av1.x, h, l); Ah[b1 + 0] = h; Al[b1 + 0] = l;
            split2(av1.y, h, l); Ah[b1 + 1] = h; Al[b1 + 1] = l;
            split2(av1.z, h, l); Ah[b1 + 2] = h; Al[b1 + 2] = l;
            split2(av1.w, h, l); Ah[b1 + 3] = h; Al[b1 + 3] = l;
        }
        // ---- B tile: 16 k x 128 n ----
        if (TRANSB == 0) {
#pragma unroll
            for (int s = 0; s < 2; s++) {
                int slot = tid + s * 256;
                int k  = slot >> 5;          // 0..15
                int n4 = (slot & 31) * 4;    // 0..124
                float4 bv = *(const float4*)(Bb + (long)(kt + k) * ldb + nBase + n4);
                float h, l;
                int idx = k * 132 + n4;
                split2(bv.x, h, l); Bh[idx + 0] = h; Bl[idx + 0] = l;
                split2(bv.y, h, l); Bh[idx + 1] = h; Bl[idx + 1] = l;
                split2(bv.z, h, l); Bh[idx + 2] = h; Bl[idx + 2] = l;
                split2(bv.w, h, l); Bh[idx + 3] = h; Bl[idx + 3] = l;
            }
        } else {
#pragma unroll
            for (int s = 0; s < 2; s++) {
                int slot = tid + s * 256;
                int n  = slot >> 2;          // 0..127
                int k4 = (slot & 3) * 4;     // 0..12
                float4 bv = *(const float4*)(Bb + (long)(nBase + n) * ldb + kt + k4);
                float h, l;
                split2(bv.x, h, l); Bh[(k4 + 0) * 132 + n] = h; Bl[(k4 + 0) * 132 + n] = l;
                split2(bv.y, h, l); Bh[(k4 + 1) * 132 + n] = h; Bl[(k4 + 1) * 132 + n] = l;
                split2(bv.z, h, l); Bh[(k4 + 2) * 132 + n] = h; Bl[(k4 + 2) * 132 + n] = l;
                split2(bv.w, h, l); Bh[(k4 + 3) * 132 + n] = h; Bl[(k4 + 3) * 132 + n] = l;
            }
        }
        __syncthreads();

#pragma unroll
        for (int kk = 0; kk < 16; kk += 8) {
            unsigned bhf[4][2], blf[4][2];
            const int brow = kk + (lane & 3);
            const int bc0  = wn + (lane >> 2);
#pragma unroll
            for (int nt = 0; nt < 4; nt++) {
                int c = bc0 + nt * 8;
                bhf[nt][0] = __float_as_uint(Bh[brow * 132 + c]);
                bhf[nt][1] = __float_as_uint(Bh[(brow + 4) * 132 + c]);
                blf[nt][0] = __float_as_uint(Bl[brow * 132 + c]);
                blf[nt][1] = __float_as_uint(Bl[(brow + 4) * 132 + c]);
            }
#pragma unroll
            for (int mt = 0; mt < 4; mt++) {
                const int am = wm + mt * 16 + (lane >> 2);
                const int ak = kk + (lane & 3);
                unsigned ahf[4], alf[4];
                ahf[0] = __float_as_uint(Ah[am * 20 + ak]);
                ahf[1] = __float_as_uint(Ah[(am + 8) * 20 + ak]);
                ahf[2] = __float_as_uint(Ah[am * 20 + ak + 4]);
                ahf[3] = __float_as_uint(Ah[(am + 8) * 20 + ak + 4]);
                alf[0] = __float_as_uint(Al[am * 20 + ak]);
                alf[1] = __float_as_uint(Al[(am + 8) * 20 + ak]);
                alf[2] = __float_as_uint(Al[am * 20 + ak + 4]);
                alf[3] = __float_as_uint(Al[(am + 8) * 20 + ak + 4]);
#pragma unroll
                for (int nt = 0; nt < 4; nt++) {
                    mma_tf32(acc[mt][nt], ahf, bhf[nt]);   // hi*hi
                    mma_tf32(acc[mt][nt], ahf, blf[nt]);   // hi*lo
                    mma_tf32(acc[mt][nt], alf, bhf[nt]);   // lo*hi
                }
            }
        }
    }

    // ---- epilogue ----
    const float* bb = bias ? (bias + (long)z * sBias) : nullptr;
    const int cc = (lane & 3) * 2;
    float bc0[4], bc1[4];
#pragma unroll
    for (int nt = 0; nt < 4; nt++) {
        int col = nBase + wn + nt * 8 + cc;
        bc0[nt] = bb ? bb[col] : 0.f;
        bc1[nt] = bb ? bb[col + 1] : 0.f;
    }
#pragma unroll
    for (int mt = 0; mt < 4; mt++) {
#pragma unroll
        for (int half = 0; half < 2; half++) {
            int r = mBase + wm + mt * 16 + (lane >> 2) + half * 8;
            if (MODE != 0 && r >= Meff) continue;
            long crow;
            float scale = 1.f;
            if (MODE == 0)      crow = (long)r * ldc;
            else if (MODE == 1) crow = (long)(rowOff + r) * ldc;
            else { int tok = perm[rowOff + r]; crow = (long)tok * ldc; scale = wsel[tok]; }
#pragma unroll
            for (int nt = 0; nt < 4; nt++) {
                int col = nBase + wn + nt * 8 + cc;
                float v0 = acc[mt][nt][half * 2 + 0] + bc0[nt];
                float v1 = acc[mt][nt][half * 2 + 1] + bc1[nt];
                if (MODE == 1) { v0 = fmaxf(v0, 0.f); v1 = fmaxf(v1, 0.f); }
                if (MODE == 2) { v0 *= scale; v1 *= scale; }
                Cb[crow + col]     = v0;
                Cb[crow + col + 1] = v1;
            }
        }
    }
}

// ---------------- row softmax over [32*SEQ, SEQ], optional causal mask ----------------
__global__ void softmax_kernel(float* __restrict__ S, int masked)
{
    const int r = blockIdx.x;
    const int q = r & (SEQ - 1);
    float* row = S + (long)r * SEQ;
    const int t = threadIdx.x;  // 256

    __shared__ float red[32];
    float v[4];
    float mx = -INFINITY;
#pragma unroll
    for (int i = 0; i < 4; i++) {
        int c = t + i * 256;
        float x = row[c];
        if (masked && c > q) x = -INFINITY;
        v[i] = x;
        mx = fmaxf(mx, x);
    }
    for (int o = 16; o; o >>= 1) mx = fmaxf(mx, __shfl_xor_sync(0xffffffffu, mx, o));
    if ((t & 31) == 0) red[t >> 5] = mx;
    __syncthreads();
    if (t < 32) {
        float m2 = (t < 8) ? red[t] : -INFINITY;
        for (int o = 4; o; o >>= 1) m2 = fmaxf(m2, __shfl_xor_sync(0xffffffffu, m2, o));
        if (t == 0) red[0] = m2;
    }
    __syncthreads();
    mx = red[0];
    __syncthreads();

    float s = 0.f;
#pragma unroll
    for (int i = 0; i < 4; i++) {
        v[i] = __expf(v[i] - mx);   // exp(-inf)=0
        s += v[i];
    }
    for (int o = 16; o; o >>= 1) s += __shfl_xor_sync(0xffffffffu, s, o);
    if ((t & 31) == 0) red[t >> 5] = s;
    __syncthreads();
    if (t < 32) {
        float s2 = (t < 8) ? red[t] : 0.f;
        for (int o = 4; o; o >>= 1) s2 += __shfl_xor_sync(0xffffffffu, s2, o);
        if (t == 0) red[0] = s2;
    }
    __syncthreads();
    float inv = 1.f / red[0];
#pragma unroll
    for (int i = 0; i < 4; i++) row[t + i * 256] = v[i] * inv;
}

// ---------------- out = LayerNorm(a + xin), row = 512 ----------------
__global__ void add_ln_kernel(const float* __restrict__ a, const float* __restrict__ xin,
                              const float* __restrict__ g, const float* __restrict__ b,
                              float* __restrict__ out)
{
    const int row = blockIdx.x;
    const int t = threadIdx.x;  // 128
    const long base = (long)row * HIDD;
    __shared__ float red[4];

    float v[4];
    float s = 0.f;
#pragma unroll
    for (int i = 0; i < 4; i++) {
        int c = t + i * 128;
        v[i] = a[base + c] + xin[base + c];
        s += v[i];
    }
    for (int o = 16; o; o >>= 1) s += __shfl_xor_sync(0xffffffffu, s, o);
    if ((t & 31) == 0) red[t >> 5] = s;
    __syncthreads();
    float mean = (red[0] + red[1] + red[2] + red[3]) * (1.f / 512.f);

    float var = 0.f;
#pragma unroll
    for (int i = 0; i < 4; i++) { float d = v[i] - mean; var += d * d; }
    for (int o = 16; o; o >>= 1) var += __shfl_xor_sync(0xffffffffu, var, o);
    __syncthreads();
    if ((t & 31) == 0) red[t >> 5] = var;
    __syncthreads();
    float rs = rsqrtf((red[0] + red[1] + red[2] + red[3]) * (1.f / 512.f) + 1e-5f);

#pragma unroll
    for (int i = 0; i < 4; i++) {
        int c = t + i * 128;
        out[base + c] = g[c] * (v[i] - mean) * rs + b[c];
    }
}

// ---------------- gating: logits -> 2nd-largest expert + weight ----------------
__global__ void gate_kernel(const float* __restrict__ x, const float* __restrict__ gw,
                            const float* __restrict__ gb, int* __restrict__ sel,
                            float* __restrict__ wsel)
{
    const int warp = threadIdx.x >> 5;
    const int lane = threadIdx.x & 31;
    const int t = blockIdx.x * 8 + warp;
    const float* xr = x + (long)t * HIDD;
    float p[8] = {0, 0, 0, 0, 0, 0, 0, 0};
    for (int k = lane; k < HIDD; k += 32) {
        float xv = xr[k];
        const float4* gwp = (const float4*)(gw + k * 8);
        float4 g0 = gwp[0], g1 = gwp[1];
        p[0] = fmaf(xv, g0.x, p[0]); p[1] = fmaf(xv, g0.y, p[1]);
        p[2] = fmaf(xv, g0.z, p[2]); p[3] = fmaf(xv, g0.w, p[3]);
        p[4] = fmaf(xv, g1.x, p[4]); p[5] = fmaf(xv, g1.y, p[5]);
        p[6] = fmaf(xv, g1.z, p[6]); p[7] = fmaf(xv, g1.w, p[7]);
    }
#pragma unroll
    for (int e = 0; e < 8; e++)
        for (int o = 16; o; o >>= 1) p[e] += __shfl_xor_sync(0xffffffffu, p[e], o);
    if (lane == 0) {
#pragma unroll
        for (int e = 0; e < 8; e++) p[e] += gb[e];
        int i1 = 0;
#pragma unroll
        for (int e = 1; e < 8; e++) if (p[e] > p[i1]) i1 = e;
        int i2 = (i1 == 0) ? 1 : 0;
#pragma unroll
        for (int e = 0; e < 8; e++) if (e != i1 && p[e] > p[i2]) i2 = e;
        sel[t]  = i2;
        wsel[t] = 1.f / (1.f + __expf(p[i1] - p[i2]));  // g2/(g1+g2)
    }
}

// ---------------- stable counting-sort of tokens by expert (single block) ----------------
__global__ void perm_kernel(const int* __restrict__ sel, int* __restrict__ perm,
                            int* __restrict__ cnt, int* __restrict__ off)
{
    __shared__ int lc[256][8];
    __shared__ int soff[9];
    const int t = threadIdx.x;
    const int t0 = t * 16;
    int c[8] = {0, 0, 0, 0, 0, 0, 0, 0};
    for (int i = 0; i < 16; i++) c[sel[t0 + i]]++;
#pragma unroll
    for (int e = 0; e < 8; e++) lc[t][e] = c[e];
    __syncthreads();
    if (t == 0) {
        int run[8] = {0, 0, 0, 0, 0, 0, 0, 0};
        for (int i = 0; i < 256; i++)
            for (int e = 0; e < 8; e++) { int tmp = lc[i][e]; lc[i][e] = run[e]; run[e] += tmp; }
        int o = 0;
        for (int e = 0; e < 8; e++) { soff[e] = o; off[e] = o; cnt[e] = run[e]; o += run[e]; }
        soff[8] = o; off[8] = o;
    }
    __syncthreads();
    int pos[8];
#pragma unroll
    for (int e = 0; e < 8; e++) pos[e] = soff[e] + lc[t][e];
    for (int i = 0; i < 16; i++) { int e = sel[t0 + i]; perm[pos[e]++] = t0 + i; }
}

// ---------------- host orchestration ----------------
extern "C" void kernel_launch(void* const* d_in, const int* in_sizes, int n_in,
                              void* d_out, int out_size)
{
    const float* x_in = (const float*)d_in[0];
    const float* enc  = (const float*)d_in[1];
    const float* wq = (const float*)d_in[2];
    const float* bq = (const float*)d_in[3];
    const float* wk = (const float*)d_in[4];
    const float* bk = (const float*)d_in[5];
    const float* wv = (const float*)d_in[6];
    const float* bv = (const float*)d_in[7];
    const float* wo = (const float*)d_in[8];
    const float* bo = (const float*)d_in[9];
    const float* gw = (const float*)d_in[10];
    const float* gb = (const float*)d_in[11];
    const float* w1 = (const float*)d_in[12];
    const float* b1 = (const float*)d_in[13];
    const float* w2 = (const float*)d_in[14];
    const float* b2 = (const float*)d_in[15];
    const float* lg = (const float*)d_in[16];
    const float* lb = (const float*)d_in[17];

    float *q, *k, *v, *s, *cat, *att, *x, *h, *moe, *wsel;
    int *sel, *perm, *cnt, *off;
    cudaGetSymbolAddress((void**)&q,    g_q);
    cudaGetSymbolAddress((void**)&k,    g_k);
    cudaGetSymbolAddress((void**)&v,    g_v);
    cudaGetSymbolAddress((void**)&s,    g_s);
    cudaGetSymbolAddress((void**)&cat,  g_cat);
    cudaGetSymbolAddress((void**)&att,  g_att);
    cudaGetSymbolAddress((void**)&x,    g_x);
    cudaGetSymbolAddress((void**)&h,    g_h);
    cudaGetSymbolAddress((void**)&moe,  g_moe);
    cudaGetSymbolAddress((void**)&sel,  g_sel);
    cudaGetSymbolAddress((void**)&wsel, g_wsel);
    cudaGetSymbolAddress((void**)&perm, g_perm);
    cudaGetSymbolAddress((void**)&cnt,  g_cnt);
    cudaGetSymbolAddress((void**)&off,  g_off);

    cudaMemcpyAsync(x, x_in, (size_t)NTOK * HIDD * sizeof(float), cudaMemcpyDeviceToDevice);

    for (int l = 0; l < NLAY; l++) {
        for (int pass = 0; pass < 2; pass++) {   // 0 = masked self-attn, 1 = cross-attn
            const int wi = l * 2 + pass;
            const float* WQ = wq + (size_t)wi * HIDD * PROJ;
            const float* WK = wk + (size_t)wi * HIDD * PROJ;
            const float* WV = wv + (size_t)wi * HIDD * PROJ;
            const float* WO = wo + (size_t)wi * PROJ * HIDD;
            const float* BQ = bq + (size_t)wi * PROJ;
            const float* BK = bk + (size_t)wi * PROJ;
            const float* BV = bv + (size_t)wi * PROJ;
            const float* BO = bo + (size_t)wi * HIDD;
            const float* qin = (pass == 0) ? x : enc;
            const float* kin = (pass == 0) ? x : enc;
            const float* vin = x;   // self: x ; cross: values from current x (faithful)

            // projections [4096,512] @ [512,4096]
            gemm_t32<0, 0><<<dim3(32, 32, 1), 256>>>(qin, WQ, BQ, q, NTOK, PROJ, HIDD,
                HIDD, PROJ, PROJ, 0, 0, 0, 0, 0, nullptr, nullptr, nullptr, nullptr);
            gemm_t32<0, 0><<<dim3(32, 32, 1), 256>>>(kin, WK, BK, k, NTOK, PROJ, HIDD,
                HIDD, PROJ, PROJ, 0, 0, 0, 0, 0, nullptr, nullptr, nullptr, nullptr);
            gemm_t32<0, 0><<<dim3(32, 32, 1), 256>>>(vin, WV, BV, v, NTOK, PROJ, HIDD,
                HIDD, PROJ, PROJ, 0, 0, 0, 0, 0, nullptr, nullptr, nullptr, nullptr);

            // scores[bh] = Q[bh] @ K[bh]^T  (32 x [1024,1024,512], NT)
            gemm_t32<1, 0><<<dim3(8, 8, 32), 256>>>(q, k, nullptr, s, SEQ, SEQ, HIDD,
                HIDD, HIDD, SEQ, 524288L, 524288L, 8388608L, 1048576L, 0,
                nullptr, nullptr, nullptr, nullptr);

            softmax_kernel<<<32 * SEQ, 256>>>(s, pass == 0 ? 1 : 0);

            // out[bh] = P @ V -> concat [b, s, h*512 + d]
            gemm_t32<0, 0><<<dim3(4, 8, 32), 256>>>(s, v, nullptr, cat, SEQ, HIDD, SEQ,
                SEQ, HIDD, PROJ, 1048576L, 524288L, 4194304L, 512L, 0,
                nullptr, nullptr, nullptr, nullptr);

            // attn out = concat @ Wo + bo
            gemm_t32<0, 0><<<dim3(4, 32, 1), 256>>>(cat, WO, BO, att, NTOK, HIDD, PROJ,
                PROJ, HIDD, HIDD, 0, 0, 0, 0, 0, nullptr, nullptr, nullptr, nullptr);

            add_ln_kernel<<<NTOK, 128>>>(att, x, lg + (size_t)(l * 3 + pass) * HIDD,
                                         lb + (size_t)(l * 3 + pass) * HIDD, x);
        }

        // ---- MoE (only the 2nd-largest expert survives, per reference quirk) ----
        gate_kernel<<<NTOK / 8, 256>>>(x, gw + (size_t)l * HIDD * NE, gb + (size_t)l * NE,
                                       sel, wsel);
        perm_kernel<<<1, 256>>>(sel, perm, cnt, off);

        gemm_t32<0, 1><<<dim3(FFN_D / 128, NTOK / 128, NE), 256>>>(
            x, w1 + (size_t)l * NE * HIDD * FFN_D, b1 + (size_t)l * NE * FFN_D, h,
            0, FFN_D, HIDD, HIDD, FFN_D, FFN_D,
            0, (long)HIDD * FFN_D, 0, 0, FFN_D, cnt, off, perm, nullptr);

        gemm_t32<0, 2><<<dim3(HIDD / 128, NTOK / 128, NE), 256>>>(
            h, w2 + (size_t)l * NE * FFN_D * HIDD, b2 + (size_t)l * NE * HIDD, moe,
            0, HIDD, FFN_D, FFN_D, HIDD, HIDD,
            0, (long)FFN_D * HIDD, 0, 0, HIDD, cnt, off, perm, wsel);

        add_ln_kernel<<<NTOK, 128>>>(moe, x, lg + (size_t)(l * 3 + 2) * HIDD,
                                     lb + (size_t)(l * 3 + 2) * HIDD, x);
    }

    cudaMemcpyAsync(d_out, x, (size_t)out_size * sizeof(float), cudaMemcpyDeviceToDevice);
}

// round 15
// speedup vs baseline: 2.1122x; 1.6608x over previous
#include <cuda_runtime.h>
#include <cuda_bf16.h>
#include <cmath>

#define NLAY 2
#define BATCH 4
#define SEQ 1024
#define HIDD 512
#define NH 8
#define NE 8
#define FFN_D 1024
#define NTOK 4096      // BATCH*SEQ
#define PROJ 4096      // NH*HIDD

// ---------------- scratch (device globals; no allocation allowed) ----------------
__device__ float g_q[(size_t)NTOK * PROJ];
__device__ float g_k[(size_t)NTOK * PROJ];
__device__ float g_v[(size_t)NTOK * PROJ];
__device__ float g_s[(size_t)32 * SEQ * SEQ];
__device__ float g_cat[(size_t)NTOK * PROJ];
__device__ float g_att[(size_t)NTOK * HIDD];
__device__ float g_x[(size_t)NTOK * HIDD];
__device__ float g_h[(size_t)NTOK * FFN_D];
__device__ float g_moe[(size_t)NTOK * HIDD];
__device__ int   g_sel[NTOK];
__device__ float g_wsel[NTOK];
__device__ int   g_perm[NTOK];
__device__ int   g_cnt[NE];
__device__ int   g_off[NE + 1];

// ---------------- bf16 split helpers ----------------
// v = hi + lo with hi = bf16_rn(v), lo = bf16_rn(v - hi). Packed as bf16x2 words.
__device__ __forceinline__ void splitpack(float v0, float v1, unsigned& hw, unsigned& lw) {
    __nv_bfloat162 h = __floats2bfloat162_rn(v0, v1);
    float2 hf = __bfloat1622float2(h);
    __nv_bfloat162 l = __floats2bfloat162_rn(v0 - hf.x, v1 - hf.y);
    hw = *(unsigned*)&h;
    lw = *(unsigned*)&l;
}

__device__ __forceinline__ void mma_bf16(float* c, const unsigned* a, const unsigned* b) {
    asm volatile(
        "mma.sync.aligned.m16n8k16.row.col.f32.bf16.bf16.f32 "
        "{%0,%1,%2,%3}, {%4,%5,%6,%7}, {%8,%9}, {%0,%1,%2,%3};\n"
        : "+f"(c[0]), "+f"(c[1]), "+f"(c[2]), "+f"(c[3])
        : "r"(a[0]), "r"(a[1]), "r"(a[2]), "r"(a[3]), "r"(b[0]), "r"(b[1]));
}

// ---------------- 128x128 GEMM, bf16 3-term split tensor cores, KT=16 ----------------
// MODE 0: normal (batched via z strides). MODE 1: MoE GEMM1 (gather A rows via perm, +bias, relu).
// MODE 2: MoE GEMM2 (A contiguous permuted, +bias, scale by wsel, scatter C rows via perm).
// Smem: A as [m][kpair] words (stride 9), B as [n][kpair] words (stride 9).
template <int TRANSB, int MODE>
__global__ void __launch_bounds__(256, 2)
gemm_bf3(const float* __restrict__ A, const float* __restrict__ B,
         const float* __restrict__ bias, float* __restrict__ C,
         int M, int N, int K, int lda, int ldb, int ldc,
         long sA, long sB, long sCb, long sCh, int sBias,
         const int* __restrict__ cnt, const int* __restrict__ off,
         const int* __restrict__ perm, const float* __restrict__ wsel)
{
    __shared__ unsigned Ahi[128 * 9], Alo[128 * 9];   // 8 kpairs + pad
    __shared__ unsigned Bhi[128 * 9], Blo[128 * 9];   // [n][kpair]

    const int z = blockIdx.z;
    const int mBase = blockIdx.y * 128;
    const int nBase = blockIdx.x * 128;

    int Meff = M;
    int rowOff = 0;
    if (MODE != 0) {
        Meff = cnt[z];
        if (mBase >= Meff) return;
        rowOff = off[z];
    }
    const float* Ab = A + (MODE == 0 ? (long)z * sA : 0L);
    const float* Bb = B + (long)z * sB;
    float* Cb = (MODE == 0) ? (C + (long)(z >> 3) * sCb + (long)(z & 7) * sCh) : C;

    const int tid  = threadIdx.x;
    const int lane = tid & 31;
    const int wid  = tid >> 5;
    const int wm   = (wid & 1) * 64;   // warp M offset (2 warps over M)
    const int wn   = (wid >> 1) * 32;  // warp N offset (4 warps over N)

    // A-load rows: thread loads rows (tid>>2) and (tid>>2)+64, 4 consecutive k each
    long aRow0, aRow1;
    {
        int r0 = mBase + (tid >> 2);
        int r1 = r0 + 64;
        if (MODE == 1) {
            int c0 = (r0 < Meff) ? r0 : (Meff - 1);
            int c1 = (r1 < Meff) ? r1 : (Meff - 1);
            aRow0 = (long)perm[rowOff + c0] * lda;
            aRow1 = (long)perm[rowOff + c1] * lda;
        } else if (MODE == 2) {
            int c0 = (r0 < Meff) ? r0 : (Meff - 1);
            int c1 = (r1 < Meff) ? r1 : (Meff - 1);
            aRow0 = (long)(rowOff + c0) * lda;
            aRow1 = (long)(rowOff + c1) * lda;
        } else {
            aRow0 = (long)r0 * lda;
            aRow1 = (long)r1 * lda;
        }
    }
    const int am0 = tid >> 2;            // smem m row (slot1: +64)
    const int ak4 = (tid & 3) * 4;       // k offset of this thread's float4
    const int akp = (tid & 3) * 2;       // kpair index of first packed word

    float acc[4][4][4];
#pragma unroll
    for (int mt = 0; mt < 4; mt++)
#pragma unroll
        for (int nt = 0; nt < 4; nt++)
#pragma unroll
            for (int c = 0; c < 4; c++) acc[mt][nt][c] = 0.f;

    for (int kt = 0; kt < K; kt += 16) {
        __syncthreads();
        // ---- A tile: 128 rows x 16 k ----
        {
            float4 av0 = *(const float4*)(Ab + aRow0 + kt + ak4);
            float4 av1 = *(const float4*)(Ab + aRow1 + kt + ak4);
            unsigned hw, lw;
            int b0 = am0 * 9 + akp;
            splitpack(av0.x, av0.y, hw, lw); Ahi[b0]     = hw; Alo[b0]     = lw;
            splitpack(av0.z, av0.w, hw, lw); Ahi[b0 + 1] = hw; Alo[b0 + 1] = lw;
            int b1 = b0 + 64 * 9;
            splitpack(av1.x, av1.y, hw, lw); Ahi[b1]     = hw; Alo[b1]     = lw;
            splitpack(av1.z, av1.w, hw, lw); Ahi[b1 + 1] = hw; Alo[b1 + 1] = lw;
        }
        // ---- B tile: 16 k x 128 n, stored [n][kpair] ----
        if (TRANSB == 0) {
#pragma unroll
            for (int s = 0; s < 4; s++) {
                int slot = tid + s * 256;      // 1024 slots = 8 kp x 128 n
                int kp = slot >> 7;            // 0..7
                int n  = slot & 127;
                float v0 = Bb[(long)(kt + 2 * kp)     * ldb + nBase + n];
                float v1 = Bb[(long)(kt + 2 * kp + 1) * ldb + nBase + n];
                unsigned hw, lw;
                splitpack(v0, v1, hw, lw);
                Bhi[n * 9 + kp] = hw; Blo[n * 9 + kp] = lw;
            }
        } else {
#pragma unroll
            for (int s = 0; s < 2; s++) {
                int slot = tid + s * 256;      // 512 slots = 128 n x 4 k4-groups
                int n  = slot >> 2;
                int k4 = (slot & 3) * 4;
                float4 bv = *(const float4*)(Bb + (long)(nBase + n) * ldb + kt + k4);
                unsigned hw, lw;
                int idx = n * 9 + (slot & 3) * 2;
                splitpack(bv.x, bv.y, hw, lw); Bhi[idx]     = hw; Blo[idx]     = lw;
                splitpack(bv.z, bv.w, hw, lw); Bhi[idx + 1] = hw; Blo[idx + 1] = lw;
            }
        }
        __syncthreads();

        // ---- one m16n8k16 step covers the whole 16-k tile ----
        unsigned bhf[4][2], blf[4][2];
        const int kp = lane & 3;
#pragma unroll
        for (int nt = 0; nt < 4; nt++) {
            int cB = wn + nt * 8 + (lane >> 2);
            bhf[nt][0] = Bhi[cB * 9 + kp];
            bhf[nt][1] = Bhi[cB * 9 + kp + 4];
            blf[nt][0] = Blo[cB * 9 + kp];
            blf[nt][1] = Blo[cB * 9 + kp + 4];
        }
#pragma unroll
        for (int mt = 0; mt < 4; mt++) {
            const int rA = wm + mt * 16 + (lane >> 2);
            unsigned ahf[4], alf[4];
            ahf[0] = Ahi[rA * 9 + kp];
            ahf[1] = Ahi[(rA + 8) * 9 + kp];
            ahf[2] = Ahi[rA * 9 + kp + 4];
            ahf[3] = Ahi[(rA + 8) * 9 + kp + 4];
            alf[0] = Alo[rA * 9 + kp];
            alf[1] = Alo[(rA + 8) * 9 + kp];
            alf[2] = Alo[rA * 9 + kp + 4];
            alf[3] = Alo[(rA + 8) * 9 + kp + 4];
#pragma unroll
            for (int nt = 0; nt < 4; nt++) {
                mma_bf16(acc[mt][nt], ahf, bhf[nt]);   // hi*hi
                mma_bf16(acc[mt][nt], ahf, blf[nt]);   // hi*lo
                mma_bf16(acc[mt][nt], alf, bhf[nt]);   // lo*hi
            }
        }
    }

    // ---- epilogue ----
    const float* bb = bias ? (bias + (long)z * sBias) : nullptr;
    const int cc = (lane & 3) * 2;
    float bc0[4], bc1[4];
#pragma unroll
    for (int nt = 0; nt < 4; nt++) {
        int col = nBase + wn + nt * 8 + cc;
        bc0[nt] = bb ? bb[col] : 0.f;
        bc1[nt] = bb ? bb[col + 1] : 0.f;
    }
#pragma unroll
    for (int mt = 0; mt < 4; mt++) {
#pragma unroll
        for (int half = 0; half < 2; half++) {
            int r = mBase + wm + mt * 16 + (lane >> 2) + half * 8;
            if (MODE != 0 && r >= Meff) continue;
            long crow;
            float scale = 1.f;
            if (MODE == 0)      crow = (long)r * ldc;
            else if (MODE == 1) crow = (long)(rowOff + r) * ldc;
            else { int tok = perm[rowOff + r]; crow = (long)tok * ldc; scale = wsel[tok]; }
#pragma unroll
            for (int nt = 0; nt < 4; nt++) {
                int col = nBase + wn + nt * 8 + cc;
                float v0 = acc[mt][nt][half * 2 + 0] + bc0[nt];
                float v1 = acc[mt][nt][half * 2 + 1] + bc1[nt];
                if (MODE == 1) { v0 = fmaxf(v0, 0.f); v1 = fmaxf(v1, 0.f); }
                if (MODE == 2) { v0 *= scale; v1 *= scale; }
                Cb[crow + col]     = v0;
                Cb[crow + col + 1] = v1;
            }
        }
    }
}

// ---------------- row softmax over [32*SEQ, SEQ], optional causal mask ----------------
__global__ void softmax_kernel(float* __restrict__ S, int masked)
{
    const int r = blockIdx.x;
    const int q = r & (SEQ - 1);
    float* row = S + (long)r * SEQ;
    const int t = threadIdx.x;  // 256

    __shared__ float red[32];
    float v[4];
    float mx = -INFINITY;
#pragma unroll
    for (int i = 0; i < 4; i++) {
        int c = t + i * 256;
        float x = row[c];
        if (masked && c > q) x = -INFINITY;
        v[i] = x;
        mx = fmaxf(mx, x);
    }
    for (int o = 16; o; o >>= 1) mx = fmaxf(mx, __shfl_xor_sync(0xffffffffu, mx, o));
    if ((t & 31) == 0) red[t >> 5] = mx;
    __syncthreads();
    if (t < 32) {
        float m2 = (t < 8) ? red[t] : -INFINITY;
        for (int o = 4; o; o >>= 1) m2 = fmaxf(m2, __shfl_xor_sync(0xffffffffu, m2, o));
        if (t == 0) red[0] = m2;
    }
    __syncthreads();
    mx = red[0];
    __syncthreads();

    float s = 0.f;
#pragma unroll
    for (int i = 0; i < 4; i++) {
        v[i] = __expf(v[i] - mx);   // exp(-inf)=0
        s += v[i];
    }
    for (int o = 16; o; o >>= 1) s += __shfl_xor_sync(0xffffffffu, s, o);
    if ((t & 31) == 0) red[t >> 5] = s;
    __syncthreads();
    if (t < 32) {
        float s2 = (t < 8) ? red[t] : 0.f;
        for (int o = 4; o; o >>= 1) s2 += __shfl_xor_sync(0xffffffffu, s2, o);
        if (t == 0) red[0] = s2;
    }
    __syncthreads();
    float inv = 1.f / red[0];
#pragma unroll
    for (int i = 0; i < 4; i++) row[t + i * 256] = v[i] * inv;
}

// ---------------- out = LayerNorm(a + xin), row = 512 ----------------
__global__ void add_ln_kernel(const float* __restrict__ a, const float* __restrict__ xin,
                              const float* __restrict__ g, const float* __restrict__ b,
                              float* __restrict__ out)
{
    const int row = blockIdx.x;
    const int t = threadIdx.x;  // 128
    const long base = (long)row * HIDD;
    __shared__ float red[4];

    float v[4];
    float s = 0.f;
#pragma unroll
    for (int i = 0; i < 4; i++) {
        int c = t + i * 128;
        v[i] = a[base + c] + xin[base + c];
        s += v[i];
    }
    for (int o = 16; o; o >>= 1) s += __shfl_xor_sync(0xffffffffu, s, o);
    if ((t & 31) == 0) red[t >> 5] = s;
    __syncthreads();
    float mean = (red[0] + red[1] + red[2] + red[3]) * (1.f / 512.f);

    float var = 0.f;
#pragma unroll
    for (int i = 0; i < 4; i++) { float d = v[i] - mean; var += d * d; }
    for (int o = 16; o; o >>= 1) var += __shfl_xor_sync(0xffffffffu, var, o);
    __syncthreads();
    if ((t & 31) == 0) red[t >> 5] = var;
    __syncthreads();
    float rs = rsqrtf((red[0] + red[1] + red[2] + red[3]) * (1.f / 512.f) + 1e-5f);

#pragma unroll
    for (int i = 0; i < 4; i++) {
        int c = t + i * 128;
        out[base + c] = g[c] * (v[i] - mean) * rs + b[c];
    }
}

// ---------------- gating: logits -> 2nd-largest expert + weight ----------------
__global__ void gate_kernel(const float* __restrict__ x, const float* __restrict__ gw,
                            const float* __restrict__ gb, int* __restrict__ sel,
                            float* __restrict__ wsel)
{
    const int warp = threadIdx.x >> 5;
    const int lane = threadIdx.x & 31;
    const int t = blockIdx.x * 8 + warp;
    const float* xr = x + (long)t * HIDD;
    float p[8] = {0, 0, 0, 0, 0, 0, 0, 0};
    for (int k = lane; k < HIDD; k += 32) {
        float xv = xr[k];
        const float4* gwp = (const float4*)(gw + k * 8);
        float4 g0 = gwp[0], g1 = gwp[1];
        p[0] = fmaf(xv, g0.x, p[0]); p[1] = fmaf(xv, g0.y, p[1]);
        p[2] = fmaf(xv, g0.z, p[2]); p[3] = fmaf(xv, g0.w, p[3]);
        p[4] = fmaf(xv, g1.x, p[4]); p[5] = fmaf(xv, g1.y, p[5]);
        p[6] = fmaf(xv, g1.z, p[6]); p[7] = fmaf(xv, g1.w, p[7]);
    }
#pragma unroll
    for (int e = 0; e < 8; e++)
        for (int o = 16; o; o >>= 1) p[e] += __shfl_xor_sync(0xffffffffu, p[e], o);
    if (lane == 0) {
#pragma unroll
        for (int e = 0; e < 8; e++) p[e] += gb[e];
        int i1 = 0;
#pragma unroll
        for (int e = 1; e < 8; e++) if (p[e] > p[i1]) i1 = e;
        int i2 = (i1 == 0) ? 1 : 0;
#pragma unroll
        for (int e = 0; e < 8; e++) if (e != i1 && p[e] > p[i2]) i2 = e;
        sel[t]  = i2;
        wsel[t] = 1.f / (1.f + __expf(p[i1] - p[i2]));  // g2/(g1+g2)
    }
}

// ---------------- stable counting-sort of tokens by expert (single block) ----------------
__global__ void perm_kernel(const int* __restrict__ sel, int* __restrict__ perm,
                            int* __restrict__ cnt, int* __restrict__ off)
{
    __shared__ int lc[256][8];
    __shared__ int soff[9];
    const int t = threadIdx.x;
    const int t0 = t * 16;
    int c[8] = {0, 0, 0, 0, 0, 0, 0, 0};
    for (int i = 0; i < 16; i++) c[sel[t0 + i]]++;
#pragma unroll
    for (int e = 0; e < 8; e++) lc[t][e] = c[e];
    __syncthreads();
    if (t == 0) {
        int run[8] = {0, 0, 0, 0, 0, 0, 0, 0};
        for (int i = 0; i < 256; i++)
            for (int e = 0; e < 8; e++) { int tmp = lc[i][e]; lc[i][e] = run[e]; run[e] += tmp; }
        int o = 0;
        for (int e = 0; e < 8; e++) { soff[e] = o; off[e] = o; cnt[e] = run[e]; o += run[e]; }
        soff[8] = o; off[8] = o;
    }
    __syncthreads();
    int pos[8];
#pragma unroll
    for (int e = 0; e < 8; e++) pos[e] = soff[e] + lc[t][e];
    for (int i = 0; i < 16; i++) { int e = sel[t0 + i]; perm[pos[e]++] = t0 + i; }
}

// ---------------- host orchestration ----------------
extern "C" void kernel_launch(void* const* d_in, const int* in_sizes, int n_in,
                              void* d_out, int out_size)
{
    const float* x_in = (const float*)d_in[0];
    const float* enc  = (const float*)d_in[1];
    const float* wq = (const float*)d_in[2];
    const float* bq = (const float*)d_in[3];
    const float* wk = (const float*)d_in[4];
    const float* bk = (const float*)d_in[5];
    const float* wv = (const float*)d_in[6];
    const float* bv = (const float*)d_in[7];
    const float* wo = (const float*)d_in[8];
    const float* bo = (const float*)d_in[9];
    const float* gw = (const float*)d_in[10];
    const float* gb = (const float*)d_in[11];
    const float* w1 = (const float*)d_in[12];
    const float* b1 = (const float*)d_in[13];
    const float* w2 = (const float*)d_in[14];
    const float* b2 = (const float*)d_in[15];
    const float* lg = (const float*)d_in[16];
    const float* lb = (const float*)d_in[17];

    float *q, *k, *v, *s, *cat, *att, *x, *h, *moe, *wsel;
    int *sel, *perm, *cnt, *off;
    cudaGetSymbolAddress((void**)&q,    g_q);
    cudaGetSymbolAddress((void**)&k,    g_k);
    cudaGetSymbolAddress((void**)&v,    g_v);
    cudaGetSymbolAddress((void**)&s,    g_s);
    cudaGetSymbolAddress((void**)&cat,  g_cat);
    cudaGetSymbolAddress((void**)&att,  g_att);
    cudaGetSymbolAddress((void**)&x,    g_x);
    cudaGetSymbolAddress((void**)&h,    g_h);
    cudaGetSymbolAddress((void**)&moe,  g_moe);
    cudaGetSymbolAddress((void**)&sel,  g_sel);
    cudaGetSymbolAddress((void**)&wsel, g_wsel);
    cudaGetSymbolAddress((void**)&perm, g_perm);
    cudaGetSymbolAddress((void**)&cnt,  g_cnt);
    cudaGetSymbolAddress((void**)&off,  g_off);

    cudaMemcpyAsync(x, x_in, (size_t)NTOK * HIDD * sizeof(float), cudaMemcpyDeviceToDevice);

    for (int l = 0; l < NLAY; l++) {
        for (int pass = 0; pass < 2; pass++) {   // 0 = masked self-attn, 1 = cross-attn
            const int wi = l * 2 + pass;
            const float* WQ = wq + (size_t)wi * HIDD * PROJ;
            const float* WK = wk + (size_t)wi * HIDD * PROJ;
            const float* WV = wv + (size_t)wi * HIDD * PROJ;
            const float* WO = wo + (size_t)wi * PROJ * HIDD;
            const float* BQ = bq + (size_t)wi * PROJ;
            const float* BK = bk + (size_t)wi * PROJ;
            const float* BV = bv + (size_t)wi * PROJ;
            const float* BO = bo + (size_t)wi * HIDD;
            const float* qin = (pass == 0) ? x : enc;
            const float* kin = (pass == 0) ? x : enc;
            const float* vin = x;   // self: x ; cross: values from current x (faithful)

            // projections [4096,512] @ [512,4096]
            gemm_bf3<0, 0><<<dim3(32, 32, 1), 256>>>(qin, WQ, BQ, q, NTOK, PROJ, HIDD,
                HIDD, PROJ, PROJ, 0, 0, 0, 0, 0, nullptr, nullptr, nullptr, nullptr);
            gemm_bf3<0, 0><<<dim3(32, 32, 1), 256>>>(kin, WK, BK, k, NTOK, PROJ, HIDD,
                HIDD, PROJ, PROJ, 0, 0, 0, 0, 0, nullptr, nullptr, nullptr, nullptr);
            gemm_bf3<0, 0><<<dim3(32, 32, 1), 256>>>(vin, WV, BV, v, NTOK, PROJ, HIDD,
                HIDD, PROJ, PROJ, 0, 0, 0, 0, 0, nullptr, nullptr, nullptr, nullptr);

            // scores[bh] = Q[bh] @ K[bh]^T  (32 x [1024,1024,512], NT)
            gemm_bf3<1, 0><<<dim3(8, 8, 32), 256>>>(q, k, nullptr, s, SEQ, SEQ, HIDD,
                HIDD, HIDD, SEQ, 524288L, 524288L, 8388608L, 1048576L, 0,
                nullptr, nullptr, nullptr, nullptr);

            softmax_kernel<<<32 * SEQ, 256>>>(s, pass == 0 ? 1 : 0);

            // out[bh] = P @ V -> concat [b, s, h*512 + d]
            gemm_bf3<0, 0><<<dim3(4, 8, 32), 256>>>(s, v, nullptr, cat, SEQ, HIDD, SEQ,
                SEQ, HIDD, PROJ, 1048576L, 524288L, 4194304L, 512L, 0,
                nullptr, nullptr, nullptr, nullptr);

            // attn out = concat @ Wo + bo
            gemm_bf3<0, 0><<<dim3(4, 32, 1), 256>>>(cat, WO, BO, att, NTOK, HIDD, PROJ,
                PROJ, HIDD, HIDD, 0, 0, 0, 0, 0, nullptr, nullptr, nullptr, nullptr);

            add_ln_kernel<<<NTOK, 128>>>(att, x, lg + (size_t)(l * 3 + pass) * HIDD,
                                         lb + (size_t)(l * 3 + pass) * HIDD, x);
        }

        // ---- MoE (only the 2nd-largest expert survives, per reference quirk) ----
        gate_kernel<<<NTOK / 8, 256>>>(x, gw + (size_t)l * HIDD * NE, gb + (size_t)l * NE,
                                       sel, wsel);
        perm_kernel<<<1, 256>>>(sel, perm, cnt, off);

        gemm_bf3<0, 1><<<dim3(FFN_D / 128, NTOK / 128, NE), 256>>>(
            x, w1 + (size_t)l * NE * HIDD * FFN_D, b1 + (size_t)l * NE * FFN_D, h,
            0, FFN_D, HIDD, HIDD, FFN_D, FFN_D,
            0, (long)HIDD * FFN_D, 0, 0, FFN_D, cnt, off, perm, nullptr);

        gemm_bf3<0, 2><<<dim3(HIDD / 128, NTOK / 128, NE), 256>>>(
            h, w2 + (size_t)l * NE * FFN_D * HIDD, b2 + (size_t)l * NE * HIDD, moe,
            0, HIDD, FFN_D, FFN_D, HIDD, HIDD,
            0, (long)FFN_D * HIDD, 0, 0, HIDD, cnt, off, perm, wsel);

        add_ln_kernel<<<NTOK, 128>>>(moe, x, lg + (size_t)(l * 3 + 2) * HIDD,
                                     lb + (size_t)(l * 3 + 2) * HIDD, x);
    }

    cudaMemcpyAsync(d_out, x, (size_t)out_size * sizeof(float), cudaMemcpyDeviceToDevice);
}